// round 17
// baseline (speedup 1.0000x reference)
#include <cuda_runtime.h>
#include <cuda_bf16.h>

// x: (256,64,25,3) f32; W_conv: (3,192) f32; W_a: (128,1) f32; out: (256,3,25,25) f32
// FINAL KERNEL (= R13/R16, measured best: ncu 6.464us, rel_err 9.5e-8, reproduced 3x).
//
// Math (all identities bench-verified):
//   mean over T commutes with every linear op:
//     xbar[j] = sum_t x[n,t,j], j=v*3+i (the 1/64 is folded into u)
//     u{1,2}[i,k] = (1/64) sum_c W_conv[i,c*3+k]*W_a[{0,64}+c]   (two 3x3 matrices)
//     s{1,2}[v,k] = sum_i xbar[v*3+i]*u{1,2}[i,k]
//   output row(0..74)=kk*25+p, col q:  e = s1[(row%3)*25+q] + s2[(row/3)*3+((row%3)+q)%3]
//   exp2 is monotone => exp2(max(e,0.2e)) = max(exp2 e, exp2 0.2e), and each branch
//   separates: exp2(e)=E1[r]*E2[c]. Precompute packed (E,F) per column; the softmax
//   hot loop is LDS.64 + mul.rn.f32x2 + FMNMX + FADD (no MUFU).
//
// Structure (each piece the winner of an A/B round):
//   - 300 loader threads x 4 LDG.128 front-batched (beat 150x8 and 75x16)
//   - loader re-index j=tid>>2,s=tid&3: the 4 same-column-quad threads are adjacent
//     lanes; 16-way T-fold = in-thread k-fold + two 64-bit shfl_xor levels
//   - u matrices on DEDICATED warps, fully hidden under x DRAM latency
//   - phase 2: 75 threads, 12 direct LDS fold, 4 ex2 each, packed scores
//   - phase 3: 4 threads/row, interleaved q=part+4j (contiguous 16B store runs),
//     k-rotation via register cycling (4 ≡ 1 mod 3)

#define TPB 448

__device__ __forceinline__ unsigned long long add2(unsigned long long a, unsigned long long b) {
    unsigned long long r;
    asm("add.rn.f32x2 %0, %1, %2;" : "=l"(r) : "l"(a), "l"(b));
    return r;
}
__device__ __forceinline__ unsigned long long mul2(unsigned long long a, unsigned long long b) {
    unsigned long long r;
    asm("mul.rn.f32x2 %0, %1, %2;" : "=l"(r) : "l"(a), "l"(b));
    return r;
}
__device__ __forceinline__ unsigned long long pack2(float lo, float hi) {
    unsigned long long r;
    asm("mov.b64 %0, {%1, %2};" : "=l"(r) : "f"(lo), "f"(hi));
    return r;
}
__device__ __forceinline__ void unpack2(unsigned long long v, float &lo, float &hi) {
    asm("mov.b64 {%0, %1}, %2;" : "=f"(lo), "=f"(hi) : "l"(v));
}
__device__ __forceinline__ float ex2a(float x) {
    float r; asm("ex2.approx.f32 %0, %1;" : "=f"(r) : "f"(x)); return r;
}

__global__ __launch_bounds__(TPB)
void gat_adj_kernel(const float* __restrict__ x,
                    const float* __restrict__ Wc,
                    const float* __restrict__ Wa,
                    float* __restrict__ out)
{
    __shared__ __align__(16) float buf[304];            // buf[i]: col i%75, group i/75
    __shared__ float uu[18];                            // [which*9+i*3+k], /64 folded
    __shared__ unsigned long long ep1[75], ep2[75];     // packed (E,F) per column

    const int n   = blockIdx.x;
    const int tid = threadIdx.x;

    if (tid < 300) {
        // ---- Loaders: j = tid>>2 (0..74), s = tid&3. float4 ids j+75s+300k. ----
        // Columns of this thread's quad: (4j+m)%75, identical for all s,k.
        const int j = tid >> 2;
        const int s = tid & 3;
        const ulonglong2* xg = reinterpret_cast<const ulonglong2*>(x)
                             + (size_t)n * 1200 + j + 75 * s;
        ulonglong2 v0 = xg[0];
        ulonglong2 v1 = xg[300];
        ulonglong2 v2 = xg[600];
        ulonglong2 v3 = xg[900];
        unsigned long long px = add2(add2(v0.x, v1.x), add2(v2.x, v3.x));
        unsigned long long py = add2(add2(v0.y, v1.y), add2(v2.y, v3.y));
        // s-fold across adjacent lanes (same j). Warp 9 has only lanes 0..11 here.
        const unsigned mask = (tid < 288) ? 0xFFFFFFFFu : 0x00000FFFu;
        px = add2(px, __shfl_xor_sync(mask, px, 1));
        py = add2(py, __shfl_xor_sync(mask, py, 1));
        px = add2(px, __shfl_xor_sync(mask, px, 2));
        py = add2(py, __shfl_xor_sync(mask, py, 2));
        if (s == 0) {
            ulonglong2 r; r.x = px; r.y = py;
            reinterpret_cast<ulonglong2*>(buf)[j] = r;   // buf[4j..4j+3]: 16-fold partial
        }
    } else if (tid >= 304) {
        // ---- u warps: 18 outputs x 8 lanes x 8 terms, overlapped with x latency ----
        const int idx = tid - 304;                      // 0..143
        const int o = idx >> 3;                         // 0..17
        const int p = idx & 7;
        const int which = o / 9;
        const int rem   = o % 9;
        const int i     = rem / 3;
        const int k     = rem % 3;
        const int c0    = p * 8;
        const float* wcb = Wc + i * 192 + k;
        const float4 wa0 = *reinterpret_cast<const float4*>(Wa + which * 64 + c0);
        const float4 wa1 = *reinterpret_cast<const float4*>(Wa + which * 64 + c0 + 4);
        float acc = wcb[(c0 + 0) * 3] * wa0.x + wcb[(c0 + 1) * 3] * wa0.y
                  + wcb[(c0 + 2) * 3] * wa0.z + wcb[(c0 + 3) * 3] * wa0.w
                  + wcb[(c0 + 4) * 3] * wa1.x + wcb[(c0 + 5) * 3] * wa1.y
                  + wcb[(c0 + 6) * 3] * wa1.z + wcb[(c0 + 7) * 3] * wa1.w;
        // warp 9 executes with lanes 16-31 only; warps 10-13 with all lanes.
        const unsigned mask = (tid < 320) ? 0xFFFF0000u : 0xFFFFFFFFu;
        acc += __shfl_xor_sync(mask, acc, 1);
        acc += __shfl_xor_sync(mask, acc, 2);
        acc += __shfl_xor_sync(mask, acc, 4);
        if (p == 0) uu[o] = acc * (1.0f / 64.0f);
    }
    __syncthreads();   // bar 0

    // ---- Phase 2: 75 threads, 12-LDS direct fold, scores + exps ----
    if (tid < 75) {
        const int k  = tid % 3;
        const int v3 = tid - k;
        const float a0 = (buf[v3]     + buf[v3 + 75]) + (buf[v3 + 150] + buf[v3 + 225]);
        const float a1 = (buf[v3 + 1] + buf[v3 + 76]) + (buf[v3 + 151] + buf[v3 + 226]);
        const float a2 = (buf[v3 + 2] + buf[v3 + 77]) + (buf[v3 + 152] + buf[v3 + 227]);

        const float s1 = a0 * uu[k]     + a1 * uu[3 + k]  + a2 * uu[6 + k];
        const float s2 = a0 * uu[9 + k] + a1 * uu[12 + k] + a2 * uu[15 + k];
        const float L2E  = 1.4426950408889634f;
        const float L2E5 = 0.2f * L2E;
        const float E1 = ex2a(s1 * L2E),  F1 = ex2a(s1 * L2E5);
        const float E2 = ex2a(s2 * L2E),  F2 = ex2a(s2 * L2E5);
        ep1[tid] = pack2(E1, F1);
        ep2[tid] = pack2(E2, F2);
    }
    __syncthreads();   // bar 1

    // ---- Phase 3: softmax, 4 threads/row, interleaved q = part + 4j ----
    {
        int row = tid >> 2;
        const bool act = (row < 75);
        if (row > 74) row = 74;                 // tid 300..447: safe duplicate work
        const int part = tid & 3;
        const int d  = row % 3;
        const int a3 = row - d;
        const int r0 = d * 25 + part;

        const unsigned long long c0 = ep2[a3];
        const unsigned long long c1 = ep2[a3 + 1];
        const unsigned long long c2 = ep2[a3 + 2];

        const int cnt = (part == 0) ? 7 : 6;    // q = part,part+4,... < 25

        // k for step j: (d + part + 4j) % 3 = (d + part + j) % 3 -> rotate +1/step
        const int kk0 = (d + part) % 3;
        unsigned long long ra = (kk0 == 0) ? c0 : ((kk0 == 1) ? c1 : c2);
        unsigned long long rb = (kk0 == 0) ? c1 : ((kk0 == 1) ? c2 : c0);
        unsigned long long rc = (kk0 == 0) ? c2 : ((kk0 == 1) ? c0 : c1);

        float vals[7];
        float sum0 = 0.f, sum1 = 0.f;
        #pragma unroll
        for (int j = 0; j < 7; j++) {
            if (j < cnt) {
                const unsigned long long pr = mul2(ep1[r0 + 4 * j], ra);
                float pe, pf;
                unpack2(pr, pe, pf);
                const float vl = fmaxf(pe, pf);   // exp2(leaky(e)) by monotonicity
                vals[j] = vl;
                if (j & 1) sum1 += vl; else sum0 += vl;
                unsigned long long t = ra; ra = rb; rb = rc; rc = t;
            }
        }
        float sum = sum0 + sum1;
        sum += __shfl_xor_sync(0xffffffffu, sum, 1);
        sum += __shfl_xor_sync(0xffffffffu, sum, 2);
        const float inv = __fdividef(1.0f, sum);

        if (act) {
            float* og = out + (size_t)n * 1875 + row * 25 + part;
            #pragma unroll
            for (int j = 0; j < 7; j++)
                if (j < cnt) og[4 * j] = vals[j] * inv;   // lanes 0-3: 16B contiguous runs
        }
    }
}

extern "C" void kernel_launch(void* const* d_in, const int* in_sizes, int n_in,
                              void* d_out, int out_size)
{
    const float* x  = (const float*)d_in[0];
    const float* Wc = (const float*)d_in[1];
    const float* Wa = (const float*)d_in[2];
    float* out = (float*)d_out;
    gat_adj_kernel<<<256, TPB>>>(x, Wc, Wa, out);
}